// round 11
// baseline (speedup 1.0000x reference)
#include <cuda_runtime.h>
#include <cuda_bf16.h>
#include <cstdint>

// ---------------------------------------------------------------------------
// VGAE/GCN encoder, round 11: column-split L2-resident aggregation with
// streaming stores + packed edge records. GEMM/scan/prep as in R10 (passing).
// ---------------------------------------------------------------------------

#define NN 50000
#define EE 800000
#define DH 512

__device__ __align__(16) float g_Xd[(size_t)NN * DH];
__device__ __align__(16) float g_h [(size_t)NN * DH];
__device__ __align__(16) __nv_bfloat16 g_Zh[(size_t)NN * DH];
__device__ __align__(16) __nv_bfloat16 g_Zl[(size_t)NN * DH];
__device__ __align__(16) __nv_bfloat16 g_W1h[512 * 512];   // [N][K]
__device__ __align__(16) __nv_bfloat16 g_W1l[512 * 512];
__device__ __align__(16) __nv_bfloat16 g_W2h[512 * 512];   // fused [Wmu|Wls]
__device__ __align__(16) __nv_bfloat16 g_W2l[512 * 512];
__device__ float g_bias2[512];
__device__ float g_dinv[NN];
__device__ int   g_deg[NN];
__device__ int   g_rowptr[NN + 1];
__device__ int   g_cursor[NN];
__device__ int2  g_edge[EE];              // (src, bits(w)) sorted by dst

// ----------------------------- threefry2x32 --------------------------------
__device__ __forceinline__ uint32_t rotl32(uint32_t v, int r) {
    return (v << r) | (v >> (32 - r));
}

__device__ __forceinline__ void threefry2x32(uint32_t k0, uint32_t k1,
                                             uint32_t& x0, uint32_t& x1) {
    uint32_t ks2 = 0x1BD11BDAu ^ k0 ^ k1;
    x0 += k0; x1 += k1;
#define TFR(r) { x0 += x1; x1 = rotl32(x1, r); x1 ^= x0; }
    TFR(13) TFR(15) TFR(26) TFR(6)
    x0 += k1;  x1 += ks2 + 1u;
    TFR(17) TFR(29) TFR(16) TFR(24)
    x0 += ks2; x1 += k0 + 2u;
    TFR(13) TFR(15) TFR(26) TFR(6)
    x0 += k0;  x1 += k1 + 3u;
    TFR(17) TFR(29) TFR(16) TFR(24)
    x0 += k1;  x1 += ks2 + 4u;
    TFR(13) TFR(15) TFR(26) TFR(6)
    x0 += ks2; x1 += k0 + 5u;
#undef TFR
}

__device__ __forceinline__ void bf16split(float w, __nv_bfloat16& h, __nv_bfloat16& l) {
    h = __float2bfloat16_rn(w);
    l = __float2bfloat16_rn(w - __bfloat162float(h));
}

// ----------------------------- graph prep ----------------------------------
__global__ void k_deg_init(int n) {
    int i = blockIdx.x * blockDim.x + threadIdx.x;
    if (i < n) g_deg[i] = 0;
}

// Fused independent prep: [deg_accum | wprep1 | wprep2 | dropout], by block.
__global__ void k_prep(const float* __restrict__ x, const int* __restrict__ dst,
                       const float* __restrict__ W1,
                       const float* __restrict__ Wmu, const float* __restrict__ Wls,
                       const float* __restrict__ bmu, const float* __restrict__ bls,
                       int E, long long T, int nbE, int nbW) {
    int b = blockIdx.x;
    int tid = threadIdx.x;
    if (b < nbE) {                                   // degree atomics
        int e = b * 256 + tid;
        if (e < E) atomicAdd(&g_deg[dst[e]], 1);
        return;
    }
    b -= nbE;
    if (b < nbW) {                                   // wprep1
        int idx = b * 256 + tid;
        int n = idx >> 9, k = idx & 511;
        bf16split(W1[k * 512 + n], g_W1h[idx], g_W1l[idx]);
        return;
    }
    b -= nbW;
    if (b < nbW) {                                   // wprep2 (+bias concat)
        int idx = b * 256 + tid;
        int n = idx >> 9, k = idx & 511;
        float w = (n < 256) ? Wmu[k * 256 + n] : Wls[k * 256 + (n - 256)];
        bf16split(w, g_W2h[idx], g_W2l[idx]);
        if (idx < 512) g_bias2[idx] = (idx < 256) ? bmu[idx] : bls[idx - 256];
        return;
    }
    b -= nbW;
    long long i = (long long)b * 256 + tid;          // dropout
    if (i >= T) return;
    uint32_t hi = 0u;
    uint32_t lo = (uint32_t)i;
    threefry2x32(0u, 42u, hi, lo);
    uint32_t bits = hi ^ lo;
    float u = __uint_as_float((bits >> 9) | 0x3f800000u) - 1.0f;
    g_Xd[i] = (u < 0.5f) ? x[i] * 2.0f : 0.0f;
}

// Tiled coalesced scan with carry; also writes g_dinv (fuses deg_finish).
__global__ void k_scan(int n) {
    __shared__ int wsum[32];
    __shared__ int s_carry;
    int tid = threadIdx.x, lane = tid & 31, w = tid >> 5;
    if (tid == 0) s_carry = 0;
    __syncthreads();
    for (int base = 0; base < n; base += 1024) {
        int i = base + tid;
        int v = (i < n) ? g_deg[i] : 0;
        if (i < n) g_dinv[i] = rsqrtf((float)v + 1.0f);
        int x = v;
#pragma unroll
        for (int o = 1; o < 32; o <<= 1) {
            int t = __shfl_up_sync(0xffffffffu, x, o);
            if (lane >= o) x += t;
        }
        if (lane == 31) wsum[w] = x;
        __syncthreads();
        if (w == 0) {
            int y = wsum[lane];
            int z = y;
#pragma unroll
            for (int o = 1; o < 32; o <<= 1) {
                int t = __shfl_up_sync(0xffffffffu, z, o);
                if (lane >= o) z += t;
            }
            wsum[lane] = z;
        }
        __syncthreads();
        int warpoff = (w == 0) ? 0 : wsum[w - 1];
        int c = s_carry;
        int excl = c + warpoff + x - v;
        if (i < n) {
            g_rowptr[i] = excl;
            g_cursor[i] = excl;
        }
        int total = wsum[31];
        __syncthreads();
        if (tid == 0) s_carry = c + total;
        __syncthreads();
    }
    if (tid == 0) g_rowptr[n] = s_carry;
}

__global__ void k_scatter(const int* __restrict__ src,
                          const int* __restrict__ dst, int E) {
    int e = blockIdx.x * blockDim.x + threadIdx.x;
    if (e >= E) return;
    int s = src[e];
    int d = dst[e];
    int pos = atomicAdd(&g_cursor[d], 1);
    g_edge[pos] = make_int2(s, __float_as_int(g_dinv[s] * g_dinv[d]));
}

// ------------------------- CSR aggregation ---------------------------------
// Column-split: blocks [0,N) -> cols 0..255, [N,2N) -> cols 256..511.
// 128 threads x float2. Streaming stores keep the gather set L2-resident.
__global__ __launch_bounds__(128)
void k_agg(int which, int N) {
    int bid = blockIdx.x;
    int half = (bid >= N) ? 1 : 0;
    int node = bid - half * N;
    int tid  = threadIdx.x;
    const float2* X2 = (const float2*)(which ? g_h : g_Xd);
    int colOff = half * 128 + tid;           // float2 units (256/row)
    float dv = g_dinv[node];
    float w0 = dv * dv;
    float2 a = X2[(size_t)node * 256 + colOff];
    float2 acc = make_float2(a.x * w0, a.y * w0);
    int e0 = g_rowptr[node];
    int e1 = g_rowptr[node + 1];
#pragma unroll 4
    for (int e = e0; e < e1; e++) {
        int2 ed = __ldg(&g_edge[e]);
        float w = __int_as_float(ed.y);
        float2 v = X2[(size_t)ed.x * 256 + colOff];
        acc.x += v.x * w;
        acc.y += v.y * w;
    }
    __nv_bfloat16 hx, lx, hy, ly;
    bf16split(acc.x, hx, lx);
    bf16split(acc.y, hy, ly);
    uint32_t hp = (uint32_t)__bfloat16_as_ushort(hx) |
                  ((uint32_t)__bfloat16_as_ushort(hy) << 16);
    uint32_t lp = (uint32_t)__bfloat16_as_ushort(lx) |
                  ((uint32_t)__bfloat16_as_ushort(ly) << 16);
    size_t o = (size_t)node * 256 + colOff;  // u32 index (512 bf16 = 256 u32)
    asm volatile("st.global.cs.u32 [%0], %1;" :: "l"((uint32_t*)g_Zh + o), "r"(hp) : "memory");
    asm volatile("st.global.cs.u32 [%0], %1;" :: "l"((uint32_t*)g_Zl + o), "r"(lp) : "memory");
}

// --------------------------- tensor GEMM -----------------------------------
#define RSTRIDE 20                       // u32 per 32-bf16 row (80 bytes)
#define MAT_U32 (128 * RSTRIDE)
#define BUF_U32 (4 * MAT_U32)
#define SMEM_GEMM (2 * BUF_U32 * 4)

__device__ __forceinline__ void mma16816(float* c, const uint32_t* a, const uint32_t* b) {
    asm volatile(
        "mma.sync.aligned.m16n8k16.row.col.f32.bf16.bf16.f32 "
        "{%0,%1,%2,%3}, {%4,%5,%6,%7}, {%8,%9}, {%0,%1,%2,%3};"
        : "+f"(c[0]), "+f"(c[1]), "+f"(c[2]), "+f"(c[3])
        : "r"(a[0]), "r"(a[1]), "r"(a[2]), "r"(a[3]), "r"(b[0]), "r"(b[1]));
}

__device__ __forceinline__ void cpa16(uint32_t dst, const void* src) {
    asm volatile("cp.async.cg.shared.global [%0], [%1], 16;"
                 :: "r"(dst), "l"(src) : "memory");
}

#define LDM4(r0, r1, r2, r3, a) \
    asm volatile("ldmatrix.sync.aligned.m8n8.x4.shared.b16 {%0,%1,%2,%3}, [%4];" \
                 : "=r"(r0), "=r"(r1), "=r"(r2), "=r"(r3) : "r"(a))

__global__ __launch_bounds__(256, 1)
void k_tgemm(const float* __restrict__ bias0, float* __restrict__ outp, int mode) {
    extern __shared__ __align__(16) uint32_t smem[];
    uint32_t sb;
    asm("{ .reg .u64 t; cvta.to.shared.u64 t, %1; cvt.u32.u64 %0, t; }"
        : "=r"(sb) : "l"(smem));

    int tid = threadIdx.x, lane = tid & 31;
    int warpId = tid >> 5;
    int warpM = warpId & 3, warpN = warpId >> 2;
    int mBase = blockIdx.y * 128;
    int nBase = blockIdx.x * 128;

    const __nv_bfloat16* Ah = g_Zh;
    const __nv_bfloat16* Al = g_Zl;
    const __nv_bfloat16* Bh = mode ? g_W2h : g_W1h;
    const __nv_bfloat16* Bl = mode ? g_W2l : g_W1l;

    float acc[2][8][4];
#pragma unroll
    for (int i = 0; i < 2; i++)
#pragma unroll
        for (int j = 0; j < 8; j++)
#pragma unroll
            for (int c = 0; c < 4; c++) acc[i][j][c] = 0.0f;

    int ck0 = tid * 2, ck1 = tid * 2 + 1;
    int r0 = ck0 >> 2, q0 = (ck0 & 3);
    int r1 = ck1 >> 2, q1 = (ck1 & 3);
    int ar0 = min(mBase + r0, NN - 1);
    int ar1 = min(mBase + r1, NN - 1);
    int br0 = nBase + r0, br1 = nBase + r1;
    uint32_t d0 = sb + (r0 * RSTRIDE + q0 * 4) * 4;
    uint32_t d1 = sb + (r1 * RSTRIDE + q1 * 4) * 4;

    auto load_tile = [&](int t, int buf) {
        int k0 = t * 32;
        uint32_t bo = buf * BUF_U32 * 4;
        size_t a0o = (size_t)ar0 * 512 + k0 + q0 * 8;
        size_t a1o = (size_t)ar1 * 512 + k0 + q1 * 8;
        size_t b0o = (size_t)br0 * 512 + k0 + q0 * 8;
        size_t b1o = (size_t)br1 * 512 + k0 + q1 * 8;
        cpa16(d0 + bo,                Ah + a0o);
        cpa16(d1 + bo,                Ah + a1o);
        cpa16(d0 + bo + MAT_U32 * 4,  Al + a0o);
        cpa16(d1 + bo + MAT_U32 * 4,  Al + a1o);
        cpa16(d0 + bo + MAT_U32 * 8,  Bh + b0o);
        cpa16(d1 + bo + MAT_U32 * 8,  Bh + b1o);
        cpa16(d0 + bo + MAT_U32 * 12, Bl + b0o);
        cpa16(d1 + bo + MAT_U32 * 12, Bl + b1o);
        asm volatile("cp.async.commit_group;" ::: "memory");
    };

    load_tile(0, 0);
    int cur = 0;

    int aRowOff = (warpM * 32 + (lane & 15)) * 80 + ((lane >> 4) << 4);
    int bRowOff = (warpN * 64 + ((lane >> 4) << 3) + (lane & 7)) * 80
                  + (((lane >> 3) & 1) << 4);

    for (int t = 0; t < 16; t++) {
        if (t + 1 < 16) {
            load_tile(t + 1, cur ^ 1);
            asm volatile("cp.async.wait_group 1;" ::: "memory");
        } else {
            asm volatile("cp.async.wait_group 0;" ::: "memory");
        }
        __syncthreads();

        uint32_t sbufAh = sb + cur * BUF_U32 * 4;
        uint32_t sbufAl = sbufAh + MAT_U32 * 4;
        uint32_t sbufBh = sbufAl + MAT_U32 * 4;
        uint32_t sbufBl = sbufBh + MAT_U32 * 4;

#pragma unroll
        for (int ks = 0; ks < 2; ks++) {
            int ko = ks * 32;
            uint32_t aH[2][4], aL[2][4], bH[8][2], bL[8][2];
#pragma unroll
            for (int mt = 0; mt < 2; mt++) {
                uint32_t ra = aRowOff + mt * 16 * 80 + ko;
                LDM4(aH[mt][0], aH[mt][1], aH[mt][2], aH[mt][3], sbufAh + ra);
                LDM4(aL[mt][0], aL[mt][1], aL[mt][2], aL[mt][3], sbufAl + ra);
            }
#pragma unroll
            for (int p = 0; p < 4; p++) {
                uint32_t rb = bRowOff + p * 16 * 80 + ko;
                LDM4(bH[2 * p][0], bH[2 * p][1], bH[2 * p + 1][0], bH[2 * p + 1][1],
                     sbufBh + rb);
                LDM4(bL[2 * p][0], bL[2 * p][1], bL[2 * p + 1][0], bL[2 * p + 1][1],
                     sbufBl + rb);
            }
#pragma unroll
            for (int mt = 0; mt < 2; mt++)
#pragma unroll
                for (int nt = 0; nt < 8; nt++) {
                    mma16816(acc[mt][nt], aH[mt], bH[nt]);
                    mma16816(acc[mt][nt], aH[mt], bL[nt]);
                    mma16816(acc[mt][nt], aL[mt], bH[nt]);
                }
        }
        __syncthreads();
        cur ^= 1;
    }

    // epilogue
    const float* bias = mode ? g_bias2 : bias0;
#pragma unroll
    for (int mt = 0; mt < 2; mt++) {
#pragma unroll
        for (int nt = 0; nt < 8; nt++) {
            int r = mBase + warpM * 32 + mt * 16 + (lane >> 2);
            int c = nBase + warpN * 64 + nt * 8 + 2 * (lane & 3);
            float b0 = bias[c], b1v = bias[c + 1];
            float v0 = acc[mt][nt][0] + b0;
            float v1 = acc[mt][nt][1] + b1v;
            float v2 = acc[mt][nt][2] + b0;
            float v3 = acc[mt][nt][3] + b1v;
            if (mode == 0) {
                v0 = fmaxf(v0, 0.0f); v1 = fmaxf(v1, 0.0f);
                v2 = fmaxf(v2, 0.0f); v3 = fmaxf(v3, 0.0f);
                if (r < NN)     *(float2*)(g_h + (size_t)r * 512 + c)       = make_float2(v0, v1);
                if (r + 8 < NN) *(float2*)(g_h + (size_t)(r + 8) * 512 + c) = make_float2(v2, v3);
            } else {
                size_t half = (c < 256) ? 0 : (size_t)NN * 256;
                int cc = (c < 256) ? c : c - 256;
                if (r < NN) {
                    float* p = outp + half + (size_t)r * 256 + cc;
                    asm volatile("st.global.cs.v2.f32 [%0], {%1, %2};"
                                 :: "l"(p), "f"(v0), "f"(v1) : "memory");
                }
                if (r + 8 < NN) {
                    float* p = outp + half + (size_t)(r + 8) * 256 + cc;
                    asm volatile("st.global.cs.v2.f32 [%0], {%1, %2};"
                                 :: "l"(p), "f"(v2), "f"(v3) : "memory");
                }
            }
        }
    }
}

// ------------------------------- launch ------------------------------------
extern "C" void kernel_launch(void* const* d_in, const int* in_sizes, int n_in,
                              void* d_out, int out_size) {
    const float* x   = (const float*)d_in[0];
    const int*   ei  = (const int*)d_in[1];
    const float* W1  = (const float*)d_in[2];
    const float* b1  = (const float*)d_in[3];
    const float* Wmu = (const float*)d_in[4];
    const float* bmu = (const float*)d_in[5];
    const float* Wls = (const float*)d_in[6];
    const float* bls = (const float*)d_in[7];
    float* out = (float*)d_out;

    int N = in_sizes[0] / DH;
    int E = in_sizes[1] / 2;
    const int* srcp = ei;
    const int* dstp = ei + E;
    long long T = (long long)N * DH;

    static bool s_init = false;
    if (!s_init) {
        cudaFuncSetAttribute(k_tgemm, cudaFuncAttributeMaxDynamicSharedMemorySize,
                             SMEM_GEMM);
        s_init = true;
    }

    int nbE = (E + 255) / 256;
    int nbW = 1024;
    int nbX = (int)((T + 255) / 256);

    k_deg_init<<<(N + 255) / 256, 256>>>(N);
    k_prep<<<nbE + 2 * nbW + nbX, 256>>>(x, dstp, W1, Wmu, Wls, bmu, bls,
                                         E, T, nbE, nbW);
    k_scan<<<1, 1024>>>(N);
    k_scatter<<<(E + 255) / 256, 256>>>(srcp, dstp, E);

    dim3 gmm(4, (N + 127) / 128);

    // layer 1
    k_agg<<<2 * N, 128>>>(0, N);
    k_tgemm<<<gmm, 256, SMEM_GEMM>>>(b1, nullptr, 0);

    // layer 2 (fused mu | logstd)
    k_agg<<<2 * N, 128>>>(1, N);
    k_tgemm<<<gmm, 256, SMEM_GEMM>>>(b1, out, 1);
}

// round 14
// speedup vs baseline: 1.1368x; 1.1368x over previous
#include <cuda_runtime.h>
#include <cuda_bf16.h>
#include <cuda_fp16.h>
#include <cstdint>

// ---------------------------------------------------------------------------
// VGAE/GCN encoder, round 12: R10 structure + fp16 gather sources.
// Xd and h stored fp16 (gather volume halved); accumulation fp32;
// GEMMs remain 3-pass bf16-split mma.sync (rel_err budget ~2e-4).
// ---------------------------------------------------------------------------

#define NN 50000
#define EE 800000
#define DH 512

__device__ __align__(16) __half g_X16[(size_t)NN * DH];    // dropout(x), fp16
__device__ __align__(16) __half g_h16[(size_t)NN * DH];    // hidden, fp16
__device__ __align__(16) __nv_bfloat16 g_Zh[(size_t)NN * DH];
__device__ __align__(16) __nv_bfloat16 g_Zl[(size_t)NN * DH];
__device__ __align__(16) __nv_bfloat16 g_W1h[512 * 512];   // [N][K]
__device__ __align__(16) __nv_bfloat16 g_W1l[512 * 512];
__device__ __align__(16) __nv_bfloat16 g_W2h[512 * 512];   // fused [Wmu|Wls]
__device__ __align__(16) __nv_bfloat16 g_W2l[512 * 512];
__device__ float g_bias2[512];
__device__ float g_dinv[NN];
__device__ int   g_deg[NN];
__device__ int   g_rowptr[NN + 1];
__device__ int   g_cursor[NN];
__device__ int2  g_edge[EE];              // (src, bits(w)) sorted by dst

// ----------------------------- threefry2x32 --------------------------------
__device__ __forceinline__ uint32_t rotl32(uint32_t v, int r) {
    return (v << r) | (v >> (32 - r));
}

__device__ __forceinline__ void threefry2x32(uint32_t k0, uint32_t k1,
                                             uint32_t& x0, uint32_t& x1) {
    uint32_t ks2 = 0x1BD11BDAu ^ k0 ^ k1;
    x0 += k0; x1 += k1;
#define TFR(r) { x0 += x1; x1 = rotl32(x1, r); x1 ^= x0; }
    TFR(13) TFR(15) TFR(26) TFR(6)
    x0 += k1;  x1 += ks2 + 1u;
    TFR(17) TFR(29) TFR(16) TFR(24)
    x0 += ks2; x1 += k0 + 2u;
    TFR(13) TFR(15) TFR(26) TFR(6)
    x0 += k0;  x1 += k1 + 3u;
    TFR(17) TFR(29) TFR(16) TFR(24)
    x0 += k1;  x1 += ks2 + 4u;
    TFR(13) TFR(15) TFR(26) TFR(6)
    x0 += ks2; x1 += k0 + 5u;
#undef TFR
}

__device__ __forceinline__ void bf16split(float w, __nv_bfloat16& h, __nv_bfloat16& l) {
    h = __float2bfloat16_rn(w);
    l = __float2bfloat16_rn(w - __bfloat162float(h));
}

// ----------------------------- graph prep ----------------------------------
__global__ void k_deg_init(int n) {
    int i = blockIdx.x * blockDim.x + threadIdx.x;
    if (i < n) g_deg[i] = 0;
}

// Fused independent prep: [deg_accum | wprep1 | wprep2 | dropout], by block.
__global__ void k_prep(const float* __restrict__ x, const int* __restrict__ dst,
                       const float* __restrict__ W1,
                       const float* __restrict__ Wmu, const float* __restrict__ Wls,
                       const float* __restrict__ bmu, const float* __restrict__ bls,
                       int E, long long T, int nbE, int nbW) {
    int b = blockIdx.x;
    int tid = threadIdx.x;
    if (b < nbE) {                                   // degree atomics
        int e = b * 256 + tid;
        if (e < E) atomicAdd(&g_deg[dst[e]], 1);
        return;
    }
    b -= nbE;
    if (b < nbW) {                                   // wprep1
        int idx = b * 256 + tid;
        int n = idx >> 9, k = idx & 511;
        bf16split(W1[k * 512 + n], g_W1h[idx], g_W1l[idx]);
        return;
    }
    b -= nbW;
    if (b < nbW) {                                   // wprep2 (+bias concat)
        int idx = b * 256 + tid;
        int n = idx >> 9, k = idx & 511;
        float w = (n < 256) ? Wmu[k * 256 + n] : Wls[k * 256 + (n - 256)];
        bf16split(w, g_W2h[idx], g_W2l[idx]);
        if (idx < 512) g_bias2[idx] = (idx < 256) ? bmu[idx] : bls[idx - 256];
        return;
    }
    b -= nbW;
    long long i = (long long)b * 256 + tid;          // dropout -> fp16
    if (i >= T) return;
    uint32_t hi = 0u;
    uint32_t lo = (uint32_t)i;
    threefry2x32(0u, 42u, hi, lo);
    uint32_t bits = hi ^ lo;
    float u = __uint_as_float((bits >> 9) | 0x3f800000u) - 1.0f;
    g_X16[i] = __float2half_rn((u < 0.5f) ? x[i] * 2.0f : 0.0f);
}

// Tiled coalesced scan with carry; also writes g_dinv (fuses deg_finish).
__global__ void k_scan(int n) {
    __shared__ int wsum[32];
    __shared__ int s_carry;
    int tid = threadIdx.x, lane = tid & 31, w = tid >> 5;
    if (tid == 0) s_carry = 0;
    __syncthreads();
    for (int base = 0; base < n; base += 1024) {
        int i = base + tid;
        int v = (i < n) ? g_deg[i] : 0;
        if (i < n) g_dinv[i] = rsqrtf((float)v + 1.0f);
        int x = v;
#pragma unroll
        for (int o = 1; o < 32; o <<= 1) {
            int t = __shfl_up_sync(0xffffffffu, x, o);
            if (lane >= o) x += t;
        }
        if (lane == 31) wsum[w] = x;
        __syncthreads();
        if (w == 0) {
            int y = wsum[lane];
            int z = y;
#pragma unroll
            for (int o = 1; o < 32; o <<= 1) {
                int t = __shfl_up_sync(0xffffffffu, z, o);
                if (lane >= o) z += t;
            }
            wsum[lane] = z;
        }
        __syncthreads();
        int warpoff = (w == 0) ? 0 : wsum[w - 1];
        int c = s_carry;
        int excl = c + warpoff + x - v;
        if (i < n) {
            g_rowptr[i] = excl;
            g_cursor[i] = excl;
        }
        int total = wsum[31];
        __syncthreads();
        if (tid == 0) s_carry = c + total;
        __syncthreads();
    }
    if (tid == 0) g_rowptr[n] = s_carry;
}

__global__ void k_scatter(const int* __restrict__ src,
                          const int* __restrict__ dst, int E) {
    int e = blockIdx.x * blockDim.x + threadIdx.x;
    if (e >= E) return;
    int s = src[e];
    int d = dst[e];
    int pos = atomicAdd(&g_cursor[d], 1);
    g_edge[pos] = make_int2(s, __float_as_int(g_dinv[s] * g_dinv[d]));
}

// ------------------------- CSR aggregation ---------------------------------
// One block (128 threads) per node, full 512-col row; fp16 gather (uint2 =
// 4 halves per thread), fp32 accumulate, bf16-split output.
__global__ __launch_bounds__(128)
void k_agg(int which) {
    int node = blockIdx.x;
    int tid  = threadIdx.x;
    const uint2* X = (const uint2*)(which ? g_h16 : g_X16);   // 128 uint2/row
    float dv = g_dinv[node];
    float w0 = dv * dv;
    uint2 a = X[(size_t)node * 128 + tid];
    float2 a01 = __half22float2(*(__half2*)&a.x);
    float2 a23 = __half22float2(*(__half2*)&a.y);
    float4 acc = make_float4(a01.x * w0, a01.y * w0, a23.x * w0, a23.y * w0);
    int e0 = g_rowptr[node];
    int e1 = g_rowptr[node + 1];
#pragma unroll 4
    for (int e = e0; e < e1; e++) {
        int2 ed = __ldg(&g_edge[e]);
        float w = __int_as_float(ed.y);
        uint2 v = X[(size_t)ed.x * 128 + tid];
        float2 v01 = __half22float2(*(__half2*)&v.x);
        float2 v23 = __half22float2(*(__half2*)&v.y);
        acc.x += v01.x * w;
        acc.y += v01.y * w;
        acc.z += v23.x * w;
        acc.w += v23.y * w;
    }
    __nv_bfloat16 hx, lx, hy, ly, hz, lz, hw, lw;
    bf16split(acc.x, hx, lx);
    bf16split(acc.y, hy, ly);
    bf16split(acc.z, hz, lz);
    bf16split(acc.w, hw, lw);
    __nv_bfloat162* Zh2 = (__nv_bfloat162*)g_Zh;
    __nv_bfloat162* Zl2 = (__nv_bfloat162*)g_Zl;
    size_t o = (size_t)node * 256 + tid * 2;
    Zh2[o]     = __nv_bfloat162(hx, hy);
    Zh2[o + 1] = __nv_bfloat162(hz, hw);
    Zl2[o]     = __nv_bfloat162(lx, ly);
    Zl2[o + 1] = __nv_bfloat162(lz, lw);
}

// --------------------------- tensor GEMM -----------------------------------
#define RSTRIDE 20                       // u32 per 32-bf16 row (80 bytes)
#define MAT_U32 (128 * RSTRIDE)
#define BUF_U32 (4 * MAT_U32)
#define SMEM_GEMM (2 * BUF_U32 * 4)

__device__ __forceinline__ void mma16816(float* c, const uint32_t* a, const uint32_t* b) {
    asm volatile(
        "mma.sync.aligned.m16n8k16.row.col.f32.bf16.bf16.f32 "
        "{%0,%1,%2,%3}, {%4,%5,%6,%7}, {%8,%9}, {%0,%1,%2,%3};"
        : "+f"(c[0]), "+f"(c[1]), "+f"(c[2]), "+f"(c[3])
        : "r"(a[0]), "r"(a[1]), "r"(a[2]), "r"(a[3]), "r"(b[0]), "r"(b[1]));
}

__device__ __forceinline__ void cpa16(uint32_t dst, const void* src) {
    asm volatile("cp.async.cg.shared.global [%0], [%1], 16;"
                 :: "r"(dst), "l"(src) : "memory");
}

#define LDM4(r0, r1, r2, r3, a) \
    asm volatile("ldmatrix.sync.aligned.m8n8.x4.shared.b16 {%0,%1,%2,%3}, [%4];" \
                 : "=r"(r0), "=r"(r1), "=r"(r2), "=r"(r3) : "r"(a))

__global__ __launch_bounds__(256, 1)
void k_tgemm(const float* __restrict__ bias0, float* __restrict__ outp, int mode) {
    extern __shared__ __align__(16) uint32_t smem[];
    uint32_t sb;
    asm("{ .reg .u64 t; cvta.to.shared.u64 t, %1; cvt.u32.u64 %0, t; }"
        : "=r"(sb) : "l"(smem));

    int tid = threadIdx.x, lane = tid & 31;
    int warpId = tid >> 5;
    int warpM = warpId & 3, warpN = warpId >> 2;
    int mBase = blockIdx.y * 128;
    int nBase = blockIdx.x * 128;

    const __nv_bfloat16* Ah = g_Zh;
    const __nv_bfloat16* Al = g_Zl;
    const __nv_bfloat16* Bh = mode ? g_W2h : g_W1h;
    const __nv_bfloat16* Bl = mode ? g_W2l : g_W1l;

    float acc[2][8][4];
#pragma unroll
    for (int i = 0; i < 2; i++)
#pragma unroll
        for (int j = 0; j < 8; j++)
#pragma unroll
            for (int c = 0; c < 4; c++) acc[i][j][c] = 0.0f;

    int ck0 = tid * 2, ck1 = tid * 2 + 1;
    int r0 = ck0 >> 2, q0 = (ck0 & 3);
    int r1 = ck1 >> 2, q1 = (ck1 & 3);
    int ar0 = min(mBase + r0, NN - 1);
    int ar1 = min(mBase + r1, NN - 1);
    int br0 = nBase + r0, br1 = nBase + r1;
    uint32_t d0 = sb + (r0 * RSTRIDE + q0 * 4) * 4;
    uint32_t d1 = sb + (r1 * RSTRIDE + q1 * 4) * 4;

    auto load_tile = [&](int t, int buf) {
        int k0 = t * 32;
        uint32_t bo = buf * BUF_U32 * 4;
        size_t a0o = (size_t)ar0 * 512 + k0 + q0 * 8;
        size_t a1o = (size_t)ar1 * 512 + k0 + q1 * 8;
        size_t b0o = (size_t)br0 * 512 + k0 + q0 * 8;
        size_t b1o = (size_t)br1 * 512 + k0 + q1 * 8;
        cpa16(d0 + bo,                Ah + a0o);
        cpa16(d1 + bo,                Ah + a1o);
        cpa16(d0 + bo + MAT_U32 * 4,  Al + a0o);
        cpa16(d1 + bo + MAT_U32 * 4,  Al + a1o);
        cpa16(d0 + bo + MAT_U32 * 8,  Bh + b0o);
        cpa16(d1 + bo + MAT_U32 * 8,  Bh + b1o);
        cpa16(d0 + bo + MAT_U32 * 12, Bl + b0o);
        cpa16(d1 + bo + MAT_U32 * 12, Bl + b1o);
        asm volatile("cp.async.commit_group;" ::: "memory");
    };

    load_tile(0, 0);
    int cur = 0;

    int aRowOff = (warpM * 32 + (lane & 15)) * 80 + ((lane >> 4) << 4);
    int bRowOff = (warpN * 64 + ((lane >> 4) << 3) + (lane & 7)) * 80
                  + (((lane >> 3) & 1) << 4);

    for (int t = 0; t < 16; t++) {
        if (t + 1 < 16) {
            load_tile(t + 1, cur ^ 1);
            asm volatile("cp.async.wait_group 1;" ::: "memory");
        } else {
            asm volatile("cp.async.wait_group 0;" ::: "memory");
        }
        __syncthreads();

        uint32_t sbufAh = sb + cur * BUF_U32 * 4;
        uint32_t sbufAl = sbufAh + MAT_U32 * 4;
        uint32_t sbufBh = sbufAl + MAT_U32 * 4;
        uint32_t sbufBl = sbufBh + MAT_U32 * 4;

#pragma unroll
        for (int ks = 0; ks < 2; ks++) {
            int ko = ks * 32;
            uint32_t aH[2][4], aL[2][4], bH[8][2], bL[8][2];
#pragma unroll
            for (int mt = 0; mt < 2; mt++) {
                uint32_t ra = aRowOff + mt * 16 * 80 + ko;
                LDM4(aH[mt][0], aH[mt][1], aH[mt][2], aH[mt][3], sbufAh + ra);
                LDM4(aL[mt][0], aL[mt][1], aL[mt][2], aL[mt][3], sbufAl + ra);
            }
#pragma unroll
            for (int p = 0; p < 4; p++) {
                uint32_t rb = bRowOff + p * 16 * 80 + ko;
                LDM4(bH[2 * p][0], bH[2 * p][1], bH[2 * p + 1][0], bH[2 * p + 1][1],
                     sbufBh + rb);
                LDM4(bL[2 * p][0], bL[2 * p][1], bL[2 * p + 1][0], bL[2 * p + 1][1],
                     sbufBl + rb);
            }
#pragma unroll
            for (int mt = 0; mt < 2; mt++)
#pragma unroll
                for (int nt = 0; nt < 8; nt++) {
                    mma16816(acc[mt][nt], aH[mt], bH[nt]);
                    mma16816(acc[mt][nt], aH[mt], bL[nt]);
                    mma16816(acc[mt][nt], aL[mt], bH[nt]);
                }
        }
        __syncthreads();
        cur ^= 1;
    }

    // epilogue
    const float* bias = mode ? g_bias2 : bias0;
#pragma unroll
    for (int mt = 0; mt < 2; mt++) {
#pragma unroll
        for (int nt = 0; nt < 8; nt++) {
            int r = mBase + warpM * 32 + mt * 16 + (lane >> 2);
            int c = nBase + warpN * 64 + nt * 8 + 2 * (lane & 3);
            float b0 = bias[c], b1v = bias[c + 1];
            float v0 = acc[mt][nt][0] + b0;
            float v1 = acc[mt][nt][1] + b1v;
            float v2 = acc[mt][nt][2] + b0;
            float v3 = acc[mt][nt][3] + b1v;
            if (mode == 0) {
                v0 = fmaxf(v0, 0.0f); v1 = fmaxf(v1, 0.0f);
                v2 = fmaxf(v2, 0.0f); v3 = fmaxf(v3, 0.0f);
                if (r < NN)
                    *(__half2*)(g_h16 + (size_t)r * 512 + c) = __floats2half2_rn(v0, v1);
                if (r + 8 < NN)
                    *(__half2*)(g_h16 + (size_t)(r + 8) * 512 + c) = __floats2half2_rn(v2, v3);
            } else {
                size_t half_off = (c < 256) ? 0 : (size_t)NN * 256;
                int cc = (c < 256) ? c : c - 256;
                if (r < NN)
                    *(float2*)(outp + half_off + (size_t)r * 256 + cc) = make_float2(v0, v1);
                if (r + 8 < NN)
                    *(float2*)(outp + half_off + (size_t)(r + 8) * 256 + cc) = make_float2(v2, v3);
            }
        }
    }
}

// ------------------------------- launch ------------------------------------
extern "C" void kernel_launch(void* const* d_in, const int* in_sizes, int n_in,
                              void* d_out, int out_size) {
    const float* x   = (const float*)d_in[0];
    const int*   ei  = (const int*)d_in[1];
    const float* W1  = (const float*)d_in[2];
    const float* b1  = (const float*)d_in[3];
    const float* Wmu = (const float*)d_in[4];
    const float* bmu = (const float*)d_in[5];
    const float* Wls = (const float*)d_in[6];
    const float* bls = (const float*)d_in[7];
    float* out = (float*)d_out;

    int N = in_sizes[0] / DH;
    int E = in_sizes[1] / 2;
    const int* srcp = ei;
    const int* dstp = ei + E;
    long long T = (long long)N * DH;

    static bool s_init = false;
    if (!s_init) {
        cudaFuncSetAttribute(k_tgemm, cudaFuncAttributeMaxDynamicSharedMemorySize,
                             SMEM_GEMM);
        s_init = true;
    }

    int nbE = (E + 255) / 256;
    int nbW = 1024;
    int nbX = (int)((T + 255) / 256);

    k_deg_init<<<(N + 255) / 256, 256>>>(N);
    k_prep<<<nbE + 2 * nbW + nbX, 256>>>(x, dstp, W1, Wmu, Wls, bmu, bls,
                                         E, T, nbE, nbW);
    k_scan<<<1, 1024>>>(N);
    k_scatter<<<(E + 255) / 256, 256>>>(srcp, dstp, E);

    dim3 gmm(4, (N + 127) / 128);

    // layer 1
    k_agg<<<N, 128>>>(0);
    k_tgemm<<<gmm, 256, SMEM_GEMM>>>(b1, nullptr, 0);

    // layer 2 (fused mu | logstd)
    k_agg<<<N, 128>>>(1);
    k_tgemm<<<gmm, 256, SMEM_GEMM>>>(b1, out, 1);
}

// round 16
// speedup vs baseline: 1.3824x; 1.2160x over previous
#include <cuda_runtime.h>
#include <cuda_fp16.h>
#include <cstdint>

// ---------------------------------------------------------------------------
// VGAE/GCN encoder, round 15: fp16 everywhere on the activation path.
//   X, h, Z stored fp16; weights fp16-split (Wh+Wl); GEMM = 2-pass mma.sync
//   m16n8k16.f16 with fp32 accum. Agg gathers fp16, accumulates fp32.
// ---------------------------------------------------------------------------

#define NN 50000
#define EE 800000
#define DH 512

__device__ __align__(16) __half g_X16[(size_t)NN * DH];    // dropout(x)
__device__ __align__(16) __half g_h16[(size_t)NN * DH];    // hidden
__device__ __align__(16) __half g_Z16[(size_t)NN * DH];    // agg output
__device__ __align__(16) __half g_W1h[512 * 512];          // [N][K] split hi
__device__ __align__(16) __half g_W1l[512 * 512];          //        split lo
__device__ __align__(16) __half g_W2h[512 * 512];          // fused [Wmu|Wls]
__device__ __align__(16) __half g_W2l[512 * 512];
__device__ float g_bias2[512];
__device__ float g_dinv[NN];
__device__ int   g_deg[NN];
__device__ int   g_rowptr[NN + 1];
__device__ int   g_cursor[NN];
__device__ int2  g_edge[EE];              // (src, bits(w)) sorted by dst

// ----------------------------- threefry2x32 --------------------------------
__device__ __forceinline__ uint32_t rotl32(uint32_t v, int r) {
    return (v << r) | (v >> (32 - r));
}

__device__ __forceinline__ void threefry2x32(uint32_t k0, uint32_t k1,
                                             uint32_t& x0, uint32_t& x1) {
    uint32_t ks2 = 0x1BD11BDAu ^ k0 ^ k1;
    x0 += k0; x1 += k1;
#define TFR(r) { x0 += x1; x1 = rotl32(x1, r); x1 ^= x0; }
    TFR(13) TFR(15) TFR(26) TFR(6)
    x0 += k1;  x1 += ks2 + 1u;
    TFR(17) TFR(29) TFR(16) TFR(24)
    x0 += ks2; x1 += k0 + 2u;
    TFR(13) TFR(15) TFR(26) TFR(6)
    x0 += k0;  x1 += k1 + 3u;
    TFR(17) TFR(29) TFR(16) TFR(24)
    x0 += k1;  x1 += ks2 + 4u;
    TFR(13) TFR(15) TFR(26) TFR(6)
    x0 += ks2; x1 += k0 + 5u;
#undef TFR
}

__device__ __forceinline__ void fp16split(float w, __half& h, __half& l) {
    h = __float2half_rn(w);
    l = __float2half_rn(w - __half2float(h));
}

// ----------------------------- graph prep ----------------------------------
__global__ void k_deg_init(int n) {
    int i = blockIdx.x * blockDim.x + threadIdx.x;
    if (i < n) g_deg[i] = 0;
}

// Fused independent prep: [deg_accum | wprep1 | wprep2 | dropout], by block.
__global__ void k_prep(const float* __restrict__ x, const int* __restrict__ dst,
                       const float* __restrict__ W1,
                       const float* __restrict__ Wmu, const float* __restrict__ Wls,
                       const float* __restrict__ bmu, const float* __restrict__ bls,
                       int E, long long T, int nbE, int nbW) {
    int b = blockIdx.x;
    int tid = threadIdx.x;
    if (b < nbE) {                                   // degree atomics
        int e = b * 256 + tid;
        if (e < E) atomicAdd(&g_deg[dst[e]], 1);
        return;
    }
    b -= nbE;
    if (b < nbW) {                                   // wprep1
        int idx = b * 256 + tid;
        int n = idx >> 9, k = idx & 511;
        fp16split(W1[k * 512 + n], g_W1h[idx], g_W1l[idx]);
        return;
    }
    b -= nbW;
    if (b < nbW) {                                   // wprep2 (+bias concat)
        int idx = b * 256 + tid;
        int n = idx >> 9, k = idx & 511;
        float w = (n < 256) ? Wmu[k * 256 + n] : Wls[k * 256 + (n - 256)];
        fp16split(w, g_W2h[idx], g_W2l[idx]);
        if (idx < 512) g_bias2[idx] = (idx < 256) ? bmu[idx] : bls[idx - 256];
        return;
    }
    b -= nbW;
    long long i = (long long)b * 256 + tid;          // dropout -> fp16
    if (i >= T) return;
    uint32_t hi = 0u;
    uint32_t lo = (uint32_t)i;
    threefry2x32(0u, 42u, hi, lo);
    uint32_t bits = hi ^ lo;
    float u = __uint_as_float((bits >> 9) | 0x3f800000u) - 1.0f;
    g_X16[i] = __float2half_rn((u < 0.5f) ? x[i] * 2.0f : 0.0f);
}

// Tiled coalesced scan with carry; also writes g_dinv (fuses deg_finish).
__global__ void k_scan(int n) {
    __shared__ int wsum[32];
    __shared__ int s_carry;
    int tid = threadIdx.x, lane = tid & 31, w = tid >> 5;
    if (tid == 0) s_carry = 0;
    __syncthreads();
    for (int base = 0; base < n; base += 1024) {
        int i = base + tid;
        int v = (i < n) ? g_deg[i] : 0;
        if (i < n) g_dinv[i] = rsqrtf((float)v + 1.0f);
        int x = v;
#pragma unroll
        for (int o = 1; o < 32; o <<= 1) {
            int t = __shfl_up_sync(0xffffffffu, x, o);
            if (lane >= o) x += t;
        }
        if (lane == 31) wsum[w] = x;
        __syncthreads();
        if (w == 0) {
            int y = wsum[lane];
            int z = y;
#pragma unroll
            for (int o = 1; o < 32; o <<= 1) {
                int t = __shfl_up_sync(0xffffffffu, z, o);
                if (lane >= o) z += t;
            }
            wsum[lane] = z;
        }
        __syncthreads();
        int warpoff = (w == 0) ? 0 : wsum[w - 1];
        int c = s_carry;
        int excl = c + warpoff + x - v;
        if (i < n) {
            g_rowptr[i] = excl;
            g_cursor[i] = excl;
        }
        int total = wsum[31];
        __syncthreads();
        if (tid == 0) s_carry = c + total;
        __syncthreads();
    }
    if (tid == 0) g_rowptr[n] = s_carry;
}

__global__ void k_scatter(const int* __restrict__ src,
                          const int* __restrict__ dst, int E) {
    int e = blockIdx.x * blockDim.x + threadIdx.x;
    if (e >= E) return;
    int s = src[e];
    int d = dst[e];
    int pos = atomicAdd(&g_cursor[d], 1);
    g_edge[pos] = make_int2(s, __float_as_int(g_dinv[s] * g_dinv[d]));
}

// ------------------------- CSR aggregation ---------------------------------
// One block (128 threads) per node; fp16 gather (uint2 = 4 halves/thread),
// fp32 accumulate, fp16 output (single matrix).
__global__ __launch_bounds__(128)
void k_agg(int which) {
    int node = blockIdx.x;
    int tid  = threadIdx.x;
    const uint2* X = (const uint2*)(which ? g_h16 : g_X16);   // 128 uint2/row
    float dv = g_dinv[node];
    float w0 = dv * dv;
    uint2 a = X[(size_t)node * 128 + tid];
    float2 a01 = __half22float2(*(__half2*)&a.x);
    float2 a23 = __half22float2(*(__half2*)&a.y);
    float4 acc = make_float4(a01.x * w0, a01.y * w0, a23.x * w0, a23.y * w0);
    int e0 = g_rowptr[node];
    int e1 = g_rowptr[node + 1];
#pragma unroll 4
    for (int e = e0; e < e1; e++) {
        int2 ed = __ldg(&g_edge[e]);
        float w = __int_as_float(ed.y);
        uint2 v = X[(size_t)ed.x * 128 + tid];
        float2 v01 = __half22float2(*(__half2*)&v.x);
        float2 v23 = __half22float2(*(__half2*)&v.y);
        acc.x += v01.x * w;
        acc.y += v01.y * w;
        acc.z += v23.x * w;
        acc.w += v23.y * w;
    }
    __half2 p01 = __floats2half2_rn(acc.x, acc.y);
    __half2 p23 = __floats2half2_rn(acc.z, acc.w);
    uint2 st;
    st.x = *(uint32_t*)&p01;
    st.y = *(uint32_t*)&p23;
    ((uint2*)g_Z16)[(size_t)node * 128 + tid] = st;
}

// --------------------------- tensor GEMM -----------------------------------
// C[M,512] = Z16 @ (Wh+Wl)^T, 2-pass fp16 mma.sync m16n8k16, fp32 accum.
// Block 128x128, 8 warps (4M x 2N), K staged 32, cp.async double buffer.
#define RSTRIDE 20                       // u32 per 32-fp16 row (80 bytes)
#define MAT_U32 (128 * RSTRIDE)
#define BUF_U32 (3 * MAT_U32)            // A, Bh, Bl
#define SMEM_GEMM (2 * BUF_U32 * 4)      // 61440 bytes

__device__ __forceinline__ void mma16816(float* c, const uint32_t* a, const uint32_t* b) {
    asm volatile(
        "mma.sync.aligned.m16n8k16.row.col.f32.f16.f16.f32 "
        "{%0,%1,%2,%3}, {%4,%5,%6,%7}, {%8,%9}, {%0,%1,%2,%3};"
        : "+f"(c[0]), "+f"(c[1]), "+f"(c[2]), "+f"(c[3])
        : "r"(a[0]), "r"(a[1]), "r"(a[2]), "r"(a[3]), "r"(b[0]), "r"(b[1]));
}

__device__ __forceinline__ void cpa16(uint32_t dst, const void* src) {
    asm volatile("cp.async.cg.shared.global [%0], [%1], 16;"
                 :: "r"(dst), "l"(src) : "memory");
}

#define LDM4(r0, r1, r2, r3, a) \
    asm volatile("ldmatrix.sync.aligned.m8n8.x4.shared.b16 {%0,%1,%2,%3}, [%4];" \
                 : "=r"(r0), "=r"(r1), "=r"(r2), "=r"(r3) : "r"(a))

__global__ __launch_bounds__(256, 1)
void k_tgemm(const float* __restrict__ bias0, float* __restrict__ outp, int mode) {
    extern __shared__ __align__(16) uint32_t smem[];
    uint32_t sb;
    asm("{ .reg .u64 t; cvta.to.shared.u64 t, %1; cvt.u32.u64 %0, t; }"
        : "=r"(sb) : "l"(smem));

    int tid = threadIdx.x, lane = tid & 31;
    int warpId = tid >> 5;
    int warpM = warpId & 3, warpN = warpId >> 2;
    int mBase = blockIdx.y * 128;
    int nBase = blockIdx.x * 128;

    const __half* A  = g_Z16;
    const __half* Bh = mode ? g_W2h : g_W1h;
    const __half* Bl = mode ? g_W2l : g_W1l;

    float acc[2][8][4];
#pragma unroll
    for (int i = 0; i < 2; i++)
#pragma unroll
        for (int j = 0; j < 8; j++)
#pragma unroll
            for (int c = 0; c < 4; c++) acc[i][j][c] = 0.0f;

    int ck0 = tid * 2, ck1 = tid * 2 + 1;
    int r0 = ck0 >> 2, q0 = (ck0 & 3);
    int r1 = ck1 >> 2, q1 = (ck1 & 3);
    int ar0 = min(mBase + r0, NN - 1);
    int ar1 = min(mBase + r1, NN - 1);
    int br0 = nBase + r0, br1 = nBase + r1;
    uint32_t d0 = sb + (r0 * RSTRIDE + q0 * 4) * 4;
    uint32_t d1 = sb + (r1 * RSTRIDE + q1 * 4) * 4;

    auto load_tile = [&](int t, int buf) {
        int k0 = t * 32;
        uint32_t bo = buf * BUF_U32 * 4;
        size_t a0o = (size_t)ar0 * 512 + k0 + q0 * 8;
        size_t a1o = (size_t)ar1 * 512 + k0 + q1 * 8;
        size_t b0o = (size_t)br0 * 512 + k0 + q0 * 8;
        size_t b1o = (size_t)br1 * 512 + k0 + q1 * 8;
        cpa16(d0 + bo,               A  + a0o);
        cpa16(d1 + bo,               A  + a1o);
        cpa16(d0 + bo + MAT_U32 * 4, Bh + b0o);
        cpa16(d1 + bo + MAT_U32 * 4, Bh + b1o);
        cpa16(d0 + bo + MAT_U32 * 8, Bl + b0o);
        cpa16(d1 + bo + MAT_U32 * 8, Bl + b1o);
        asm volatile("cp.async.commit_group;" ::: "memory");
    };

    load_tile(0, 0);
    int cur = 0;

    int aRowOff = (warpM * 32 + (lane & 15)) * 80 + ((lane >> 4) << 4);
    int bRowOff = (warpN * 64 + ((lane >> 4) << 3) + (lane & 7)) * 80
                  + (((lane >> 3) & 1) << 4);

    for (int t = 0; t < 16; t++) {
        if (t + 1 < 16) {
            load_tile(t + 1, cur ^ 1);
            asm volatile("cp.async.wait_group 1;" ::: "memory");
        } else {
            asm volatile("cp.async.wait_group 0;" ::: "memory");
        }
        __syncthreads();

        uint32_t sbufA  = sb + cur * BUF_U32 * 4;
        uint32_t sbufBh = sbufA + MAT_U32 * 4;
        uint32_t sbufBl = sbufBh + MAT_U32 * 4;

#pragma unroll
        for (int ks = 0; ks < 2; ks++) {
            int ko = ks * 32;
            uint32_t aF[2][4], bH[8][2], bL[8][2];
#pragma unroll
            for (int mt = 0; mt < 2; mt++) {
                uint32_t ra = aRowOff + mt * 16 * 80 + ko;
                LDM4(aF[mt][0], aF[mt][1], aF[mt][2], aF[mt][3], sbufA + ra);
            }
#pragma unroll
            for (int p = 0; p < 4; p++) {
                uint32_t rb = bRowOff + p * 16 * 80 + ko;
                LDM4(bH[2 * p][0], bH[2 * p][1], bH[2 * p + 1][0], bH[2 * p + 1][1],
                     sbufBh + rb);
                LDM4(bL[2 * p][0], bL[2 * p][1], bL[2 * p + 1][0], bL[2 * p + 1][1],
                     sbufBl + rb);
            }
#pragma unroll
            for (int mt = 0; mt < 2; mt++)
#pragma unroll
                for (int nt = 0; nt < 8; nt++) {
                    mma16816(acc[mt][nt], aF[mt], bH[nt]);
                    mma16816(acc[mt][nt], aF[mt], bL[nt]);
                }
        }
        __syncthreads();
        cur ^= 1;
    }

    // epilogue
    const float* bias = mode ? g_bias2 : bias0;
#pragma unroll
    for (int mt = 0; mt < 2; mt++) {
#pragma unroll
        for (int nt = 0; nt < 8; nt++) {
            int r = mBase + warpM * 32 + mt * 16 + (lane >> 2);
            int c = nBase + warpN * 64 + nt * 8 + 2 * (lane & 3);
            float b0 = bias[c], b1v = bias[c + 1];
            float v0 = acc[mt][nt][0] + b0;
            float v1 = acc[mt][nt][1] + b1v;
            float v2 = acc[mt][nt][2] + b0;
            float v3 = acc[mt][nt][3] + b1v;
            if (mode == 0) {
                v0 = fmaxf(v0, 0.0f); v1 = fmaxf(v1, 0.0f);
                v2 = fmaxf(v2, 0.0f); v3 = fmaxf(v3, 0.0f);
                if (r < NN)
                    *(__half2*)(g_h16 + (size_t)r * 512 + c) = __floats2half2_rn(v0, v1);
                if (r + 8 < NN)
                    *(__half2*)(g_h16 + (size_t)(r + 8) * 512 + c) = __floats2half2_rn(v2, v3);
            } else {
                size_t half_off = (c < 256) ? 0 : (size_t)NN * 256;
                int cc = (c < 256) ? c : c - 256;
                if (r < NN)
                    *(float2*)(outp + half_off + (size_t)r * 256 + cc) = make_float2(v0, v1);
                if (r + 8 < NN)
                    *(float2*)(outp + half_off + (size_t)(r + 8) * 256 + cc) = make_float2(v2, v3);
            }
        }
    }
}

// ------------------------------- launch ------------------------------------
extern "C" void kernel_launch(void* const* d_in, const int* in_sizes, int n_in,
                              void* d_out, int out_size) {
    const float* x   = (const float*)d_in[0];
    const int*   ei  = (const int*)d_in[1];
    const float* W1  = (const float*)d_in[2];
    const float* b1  = (const float*)d_in[3];
    const float* Wmu = (const float*)d_in[4];
    const float* bmu = (const float*)d_in[5];
    const float* Wls = (const float*)d_in[6];
    const float* bls = (const float*)d_in[7];
    float* out = (float*)d_out;

    int N = in_sizes[0] / DH;
    int E = in_sizes[1] / 2;
    const int* srcp = ei;
    const int* dstp = ei + E;
    long long T = (long long)N * DH;

    static bool s_init = false;
    if (!s_init) {
        cudaFuncSetAttribute(k_tgemm, cudaFuncAttributeMaxDynamicSharedMemorySize,
                             SMEM_GEMM);
        s_init = true;
    }

    int nbE = (E + 255) / 256;
    int nbW = 1024;
    int nbX = (int)((T + 255) / 256);

    k_deg_init<<<(N + 255) / 256, 256>>>(N);
    k_prep<<<nbE + 2 * nbW + nbX, 256>>>(x, dstp, W1, Wmu, Wls, bmu, bls,
                                         E, T, nbE, nbW);
    k_scan<<<1, 1024>>>(N);
    k_scatter<<<(E + 255) / 256, 256>>>(srcp, dstp, E);

    dim3 gmm(4, (N + 127) / 128);

    // layer 1
    k_agg<<<N, 128>>>(0);
    k_tgemm<<<gmm, 256, SMEM_GEMM>>>(b1, nullptr, 0);

    // layer 2 (fused mu | logstd)
    k_agg<<<N, 128>>>(1);
    k_tgemm<<<gmm, 256, SMEM_GEMM>>>(b1, out, 1);
}

// round 17
// speedup vs baseline: 2.0119x; 1.4554x over previous
#include <cuda_runtime.h>
#include <cuda_fp16.h>
#include <cstdint>

// ---------------------------------------------------------------------------
// VGAE/GCN encoder, round 17: single-pass fp16 GEMM (weights fp16, one MMA
// pass), stream-forked dropout overlapping the degree/CSR chain.
// Activation path fp16 end-to-end, fp32 accumulation everywhere.
// ---------------------------------------------------------------------------

#define NN 50000
#define EE 800000
#define DH 512

__device__ __align__(16) __half g_X16[(size_t)NN * DH];    // dropout(x)
__device__ __align__(16) __half g_h16[(size_t)NN * DH];    // hidden
__device__ __align__(16) __half g_Z16[(size_t)NN * DH];    // agg output
__device__ __align__(16) __half g_W1[512 * 512];           // [N][K] fp16
__device__ __align__(16) __half g_W2[512 * 512];           // fused [Wmu|Wls]
__device__ float g_bias2[512];
__device__ float g_dinv[NN];
__device__ int   g_deg[NN];
__device__ int   g_rowptr[NN + 1];
__device__ int   g_cursor[NN];
__device__ int2  g_edge[EE];              // (src, bits(w)) sorted by dst

// ----------------------------- threefry2x32 --------------------------------
__device__ __forceinline__ uint32_t rotl32(uint32_t v, int r) {
    return (v << r) | (v >> (32 - r));
}

__device__ __forceinline__ void threefry2x32(uint32_t k0, uint32_t k1,
                                             uint32_t& x0, uint32_t& x1) {
    uint32_t ks2 = 0x1BD11BDAu ^ k0 ^ k1;
    x0 += k0; x1 += k1;
#define TFR(r) { x0 += x1; x1 = rotl32(x1, r); x1 ^= x0; }
    TFR(13) TFR(15) TFR(26) TFR(6)
    x0 += k1;  x1 += ks2 + 1u;
    TFR(17) TFR(29) TFR(16) TFR(24)
    x0 += ks2; x1 += k0 + 2u;
    TFR(13) TFR(15) TFR(26) TFR(6)
    x0 += k0;  x1 += k1 + 3u;
    TFR(17) TFR(29) TFR(16) TFR(24)
    x0 += k1;  x1 += ks2 + 4u;
    TFR(13) TFR(15) TFR(26) TFR(6)
    x0 += ks2; x1 += k0 + 5u;
#undef TFR
}

// ----------------------------- graph prep ----------------------------------
__global__ void k_deg_init(int n) {
    int i = blockIdx.x * blockDim.x + threadIdx.x;
    if (i < n) g_deg[i] = 0;
}

// Fused independent prep: [deg_accum | wprep1 | wprep2], by block range.
__global__ void k_prep(const int* __restrict__ dst,
                       const float* __restrict__ W1,
                       const float* __restrict__ Wmu, const float* __restrict__ Wls,
                       const float* __restrict__ bmu, const float* __restrict__ bls,
                       int E, int nbE, int nbW) {
    int b = blockIdx.x;
    int tid = threadIdx.x;
    if (b < nbE) {                                   // degree atomics
        int e = b * 256 + tid;
        if (e < E) atomicAdd(&g_deg[dst[e]], 1);
        return;
    }
    b -= nbE;
    if (b < nbW) {                                   // wprep1
        int idx = b * 256 + tid;
        int n = idx >> 9, k = idx & 511;
        g_W1[idx] = __float2half_rn(W1[k * 512 + n]);
        return;
    }
    b -= nbW;
    {                                                // wprep2 (+bias concat)
        int idx = b * 256 + tid;
        int n = idx >> 9, k = idx & 511;
        float w = (n < 256) ? Wmu[k * 256 + n] : Wls[k * 256 + (n - 256)];
        g_W2[idx] = __float2half_rn(w);
        if (idx < 512) g_bias2[idx] = (idx < 256) ? bmu[idx] : bls[idx - 256];
    }
}

// Dropout (runs on forked stream, overlaps deg/scan/scatter chain).
__global__ void k_dropout(const float* __restrict__ x, long long T) {
    long long i = (long long)blockIdx.x * blockDim.x + threadIdx.x;
    if (i >= T) return;
    uint32_t hi = 0u;
    uint32_t lo = (uint32_t)i;
    threefry2x32(0u, 42u, hi, lo);
    uint32_t bits = hi ^ lo;
    float u = __uint_as_float((bits >> 9) | 0x3f800000u) - 1.0f;
    g_X16[i] = __float2half_rn((u < 0.5f) ? x[i] * 2.0f : 0.0f);
}

// Tiled coalesced scan with carry; also writes g_dinv.
__global__ void k_scan(int n) {
    __shared__ int wsum[32];
    __shared__ int s_carry;
    int tid = threadIdx.x, lane = tid & 31, w = tid >> 5;
    if (tid == 0) s_carry = 0;
    __syncthreads();
    for (int base = 0; base < n; base += 1024) {
        int i = base + tid;
        int v = (i < n) ? g_deg[i] : 0;
        if (i < n) g_dinv[i] = rsqrtf((float)v + 1.0f);
        int x = v;
#pragma unroll
        for (int o = 1; o < 32; o <<= 1) {
            int t = __shfl_up_sync(0xffffffffu, x, o);
            if (lane >= o) x += t;
        }
        if (lane == 31) wsum[w] = x;
        __syncthreads();
        if (w == 0) {
            int y = wsum[lane];
            int z = y;
#pragma unroll
            for (int o = 1; o < 32; o <<= 1) {
                int t = __shfl_up_sync(0xffffffffu, z, o);
                if (lane >= o) z += t;
            }
            wsum[lane] = z;
        }
        __syncthreads();
        int warpoff = (w == 0) ? 0 : wsum[w - 1];
        int c = s_carry;
        int excl = c + warpoff + x - v;
        if (i < n) {
            g_rowptr[i] = excl;
            g_cursor[i] = excl;
        }
        int total = wsum[31];
        __syncthreads();
        if (tid == 0) s_carry = c + total;
        __syncthreads();
    }
    if (tid == 0) g_rowptr[n] = s_carry;
}

__global__ void k_scatter(const int* __restrict__ src,
                          const int* __restrict__ dst, int E) {
    int e = blockIdx.x * blockDim.x + threadIdx.x;
    if (e >= E) return;
    int s = src[e];
    int d = dst[e];
    int pos = atomicAdd(&g_cursor[d], 1);
    g_edge[pos] = make_int2(s, __float_as_int(g_dinv[s] * g_dinv[d]));
}

// ------------------------- CSR aggregation ---------------------------------
__global__ __launch_bounds__(128)
void k_agg(int which) {
    int node = blockIdx.x;
    int tid  = threadIdx.x;
    const uint2* X = (const uint2*)(which ? g_h16 : g_X16);   // 128 uint2/row
    float dv = g_dinv[node];
    float w0 = dv * dv;
    uint2 a = X[(size_t)node * 128 + tid];
    float2 a01 = __half22float2(*(__half2*)&a.x);
    float2 a23 = __half22float2(*(__half2*)&a.y);
    float4 acc = make_float4(a01.x * w0, a01.y * w0, a23.x * w0, a23.y * w0);
    int e0 = g_rowptr[node];
    int e1 = g_rowptr[node + 1];
#pragma unroll 4
    for (int e = e0; e < e1; e++) {
        int2 ed = __ldg(&g_edge[e]);
        float w = __int_as_float(ed.y);
        uint2 v = X[(size_t)ed.x * 128 + tid];
        float2 v01 = __half22float2(*(__half2*)&v.x);
        float2 v23 = __half22float2(*(__half2*)&v.y);
        acc.x += v01.x * w;
        acc.y += v01.y * w;
        acc.z += v23.x * w;
        acc.w += v23.y * w;
    }
    __half2 p01 = __floats2half2_rn(acc.x, acc.y);
    __half2 p23 = __floats2half2_rn(acc.z, acc.w);
    uint2 st;
    st.x = *(uint32_t*)&p01;
    st.y = *(uint32_t*)&p23;
    ((uint2*)g_Z16)[(size_t)node * 128 + tid] = st;
}

// --------------------------- tensor GEMM -----------------------------------
// C[M,512] = Z16 @ W^T, single-pass fp16 mma.sync m16n8k16, fp32 accum.
// Block 128x128, 8 warps, K staged 32, cp.async double buffer, 2 CTAs/SM.
#define RSTRIDE 20                       // u32 per 32-fp16 row (80 bytes)
#define MAT_U32 (128 * RSTRIDE)
#define BUF_U32 (2 * MAT_U32)            // A, B
#define SMEM_GEMM (2 * BUF_U32 * 4)      // 40960 bytes

__device__ __forceinline__ void mma16816(float* c, const uint32_t* a, const uint32_t* b) {
    asm volatile(
        "mma.sync.aligned.m16n8k16.row.col.f32.f16.f16.f32 "
        "{%0,%1,%2,%3}, {%4,%5,%6,%7}, {%8,%9}, {%0,%1,%2,%3};"
        : "+f"(c[0]), "+f"(c[1]), "+f"(c[2]), "+f"(c[3])
        : "r"(a[0]), "r"(a[1]), "r"(a[2]), "r"(a[3]), "r"(b[0]), "r"(b[1]));
}

__device__ __forceinline__ void cpa16(uint32_t dst, const void* src) {
    asm volatile("cp.async.cg.shared.global [%0], [%1], 16;"
                 :: "r"(dst), "l"(src) : "memory");
}

#define LDM4(r0, r1, r2, r3, a) \
    asm volatile("ldmatrix.sync.aligned.m8n8.x4.shared.b16 {%0,%1,%2,%3}, [%4];" \
                 : "=r"(r0), "=r"(r1), "=r"(r2), "=r"(r3) : "r"(a))

__global__ __launch_bounds__(256, 2)
void k_tgemm(const float* __restrict__ bias0, float* __restrict__ outp, int mode) {
    extern __shared__ __align__(16) uint32_t smem[];
    uint32_t sb;
    asm("{ .reg .u64 t; cvta.to.shared.u64 t, %1; cvt.u32.u64 %0, t; }"
        : "=r"(sb) : "l"(smem));

    int tid = threadIdx.x, lane = tid & 31;
    int warpId = tid >> 5;
    int warpM = warpId & 3, warpN = warpId >> 2;
    int mBase = blockIdx.y * 128;
    int nBase = blockIdx.x * 128;

    const __half* A = g_Z16;
    const __half* B = mode ? g_W2 : g_W1;

    float acc[2][8][4];
#pragma unroll
    for (int i = 0; i < 2; i++)
#pragma unroll
        for (int j = 0; j < 8; j++)
#pragma unroll
            for (int c = 0; c < 4; c++) acc[i][j][c] = 0.0f;

    int ck0 = tid * 2, ck1 = tid * 2 + 1;
    int r0 = ck0 >> 2, q0 = (ck0 & 3);
    int r1 = ck1 >> 2, q1 = (ck1 & 3);
    int ar0 = min(mBase + r0, NN - 1);
    int ar1 = min(mBase + r1, NN - 1);
    int br0 = nBase + r0, br1 = nBase + r1;
    uint32_t d0 = sb + (r0 * RSTRIDE + q0 * 4) * 4;
    uint32_t d1 = sb + (r1 * RSTRIDE + q1 * 4) * 4;

    auto load_tile = [&](int t, int buf) {
        int k0 = t * 32;
        uint32_t bo = buf * BUF_U32 * 4;
        cpa16(d0 + bo,               A + (size_t)ar0 * 512 + k0 + q0 * 8);
        cpa16(d1 + bo,               A + (size_t)ar1 * 512 + k0 + q1 * 8);
        cpa16(d0 + bo + MAT_U32 * 4, B + (size_t)br0 * 512 + k0 + q0 * 8);
        cpa16(d1 + bo + MAT_U32 * 4, B + (size_t)br1 * 512 + k0 + q1 * 8);
        asm volatile("cp.async.commit_group;" ::: "memory");
    };

    load_tile(0, 0);
    int cur = 0;

    int aRowOff = (warpM * 32 + (lane & 15)) * 80 + ((lane >> 4) << 4);
    int bRowOff = (warpN * 64 + ((lane >> 4) << 3) + (lane & 7)) * 80
                  + (((lane >> 3) & 1) << 4);

    for (int t = 0; t < 16; t++) {
        if (t + 1 < 16) {
            load_tile(t + 1, cur ^ 1);
            asm volatile("cp.async.wait_group 1;" ::: "memory");
        } else {
            asm volatile("cp.async.wait_group 0;" ::: "memory");
        }
        __syncthreads();

        uint32_t sbufA = sb + cur * BUF_U32 * 4;
        uint32_t sbufB = sbufA + MAT_U32 * 4;

#pragma unroll
        for (int ks = 0; ks < 2; ks++) {
            int ko = ks * 32;
            uint32_t aF[2][4], bF[8][2];
#pragma unroll
            for (int mt = 0; mt < 2; mt++) {
                uint32_t ra = aRowOff + mt * 16 * 80 + ko;
                LDM4(aF[mt][0], aF[mt][1], aF[mt][2], aF[mt][3], sbufA + ra);
            }
#pragma unroll
            for (int p = 0; p < 4; p++) {
                uint32_t rb = bRowOff + p * 16 * 80 + ko;
                LDM4(bF[2 * p][0], bF[2 * p][1], bF[2 * p + 1][0], bF[2 * p + 1][1],
                     sbufB + rb);
            }
#pragma unroll
            for (int mt = 0; mt < 2; mt++)
#pragma unroll
                for (int nt = 0; nt < 8; nt++)
                    mma16816(acc[mt][nt], aF[mt], bF[nt]);
        }
        __syncthreads();
        cur ^= 1;
    }

    // epilogue
    const float* bias = mode ? g_bias2 : bias0;
#pragma unroll
    for (int mt = 0; mt < 2; mt++) {
#pragma unroll
        for (int nt = 0; nt < 8; nt++) {
            int r = mBase + warpM * 32 + mt * 16 + (lane >> 2);
            int c = nBase + warpN * 64 + nt * 8 + 2 * (lane & 3);
            float b0 = bias[c], b1v = bias[c + 1];
            float v0 = acc[mt][nt][0] + b0;
            float v1 = acc[mt][nt][1] + b1v;
            float v2 = acc[mt][nt][2] + b0;
            float v3 = acc[mt][nt][3] + b1v;
            if (mode == 0) {
                v0 = fmaxf(v0, 0.0f); v1 = fmaxf(v1, 0.0f);
                v2 = fmaxf(v2, 0.0f); v3 = fmaxf(v3, 0.0f);
                if (r < NN)
                    *(__half2*)(g_h16 + (size_t)r * 512 + c) = __floats2half2_rn(v0, v1);
                if (r + 8 < NN)
                    *(__half2*)(g_h16 + (size_t)(r + 8) * 512 + c) = __floats2half2_rn(v2, v3);
            } else {
                size_t half_off = (c < 256) ? 0 : (size_t)NN * 256;
                int cc = (c < 256) ? c : c - 256;
                if (r < NN)
                    *(float2*)(outp + half_off + (size_t)r * 256 + cc) = make_float2(v0, v1);
                if (r + 8 < NN)
                    *(float2*)(outp + half_off + (size_t)(r + 8) * 256 + cc) = make_float2(v2, v3);
            }
        }
    }
}

// ------------------------------- launch ------------------------------------
extern "C" void kernel_launch(void* const* d_in, const int* in_sizes, int n_in,
                              void* d_out, int out_size) {
    const float* x   = (const float*)d_in[0];
    const int*   ei  = (const int*)d_in[1];
    const float* W1  = (const float*)d_in[2];
    const float* b1  = (const float*)d_in[3];
    const float* Wmu = (const float*)d_in[4];
    const float* bmu = (const float*)d_in[5];
    const float* Wls = (const float*)d_in[6];
    const float* bls = (const float*)d_in[7];
    float* out = (float*)d_out;

    int N = in_sizes[0] / DH;
    int E = in_sizes[1] / 2;
    const int* srcp = ei;
    const int* dstp = ei + E;
    long long T = (long long)N * DH;

    static bool s_init = false;
    static cudaStream_t s2 = nullptr;
    static cudaEvent_t evFork = nullptr, evJoin = nullptr;
    if (!s_init) {
        cudaFuncSetAttribute(k_tgemm, cudaFuncAttributeMaxDynamicSharedMemorySize,
                             SMEM_GEMM);
        cudaStreamCreateWithFlags(&s2, cudaStreamNonBlocking);
        cudaEventCreateWithFlags(&evFork, cudaEventDisableTiming);
        cudaEventCreateWithFlags(&evJoin, cudaEventDisableTiming);
        s_init = true;
    }

    int nbE = (E + 255) / 256;
    int nbW = 1024;
    int nbX = (int)((T + 255) / 256);

    // fork: dropout on s2, overlapping the degree/CSR chain on stream 0
    cudaEventRecord(evFork, 0);
    cudaStreamWaitEvent(s2, evFork, 0);
    k_dropout<<<nbX, 256, 0, s2>>>(x, T);
    cudaEventRecord(evJoin, s2);

    k_deg_init<<<(N + 255) / 256, 256>>>(N);
    k_prep<<<nbE + 2 * nbW, 256>>>(dstp, W1, Wmu, Wls, bmu, bls, E, nbE, nbW);
    k_scan<<<1, 1024>>>(N);
    k_scatter<<<(E + 255) / 256, 256>>>(srcp, dstp, E);

    // join before first aggregation (needs dropout output)
    cudaStreamWaitEvent(0, evJoin, 0);

    dim3 gmm(4, (N + 127) / 128);

    // layer 1
    k_agg<<<N, 128>>>(0);
    k_tgemm<<<gmm, 256, SMEM_GEMM>>>(b1, nullptr, 0);

    // layer 2 (fused mu | logstd)
    k_agg<<<N, 128>>>(1);
    k_tgemm<<<gmm, 256, SMEM_GEMM>>>(b1, out, 1);
}